// round 1
// baseline (speedup 1.0000x reference)
#include <cuda_runtime.h>
#include <math.h>

#define NN 100000
#define EE 1600000
#define CC 128
#define HH 64
#define GG 512

// ---------------- scratch (device globals: allocation-free) ----------------
__device__ float4 g_agg1[NN * (CC / 4)];   // 51.2 MB, zeroed only at kept rows
__device__ float4 g_out1[NN * (HH / 4)];   // 25.6 MB, written only at kept rows
__device__ float4 g_agg2[NN * (HH / 4)];   // 25.6 MB, zeroed only at kept rows
__device__ float g_raw[NN];
__device__ float g_score[NN];
__device__ unsigned char g_mask[NN];
__device__ float g_gmax[GG];
__device__ float g_gz[GG];
__device__ float g_gsmax[GG];
__device__ float g_kl[GG];
__device__ float g_cnt[GG];
__device__ float g_go[GG * HH];
__device__ int g_nkept;

// ---------------- helpers ----------------
__device__ __forceinline__ void red_add_v4(float4* a, float4 v) {
    asm volatile("red.global.add.v4.f32 [%0], {%1,%2,%3,%4};"
                 :: "l"(a), "f"(v.x), "f"(v.y), "f"(v.z), "f"(v.w) : "memory");
}

__device__ __forceinline__ void atomicMaxF(float* addr, float v) {
    int* ai = (int*)addr;
    int old = *ai;
    while (__int_as_float(old) < v) {
        int prev = atomicCAS(ai, old, __float_as_int(v));
        if (prev == old) break;
        old = prev;
    }
}

// ---------------- kernels ----------------
__global__ void k_init() {
    int t = blockIdx.x * blockDim.x + threadIdx.x;
    if (t < GG * HH) g_go[t] = 0.f;
    if (t < GG) {
        g_gz[t] = 0.f; g_gsmax[t] = 0.f; g_kl[t] = 0.f; g_cnt[t] = 0.f;
        g_gmax[t] = -INFINITY;
    }
    if (t == 0) g_nkept = 0;
}

// raw[n] = dot(x[n], pool_w); segment max -> g_gmax.  One warp per node.
__global__ void k_raw(const float4* __restrict__ x4, const float4* __restrict__ pw4,
                      const int* __restrict__ batch) {
    int gt = blockIdx.x * blockDim.x + threadIdx.x;
    int n = gt >> 5;
    int lane = gt & 31;
    if (n >= NN) return;
    float4 v = x4[n * 32 + lane];
    float4 w = pw4[lane];
    float s = v.x * w.x + v.y * w.y + v.z * w.z + v.w * w.w;
    #pragma unroll
    for (int o = 16; o; o >>= 1) s += __shfl_down_sync(0xffffffffu, s, o);
    if (lane == 0) {
        g_raw[n] = s;
        atomicMaxF(&g_gmax[batch[n]], s);
    }
}

__global__ void k_exp(const int* __restrict__ batch) {
    int n = blockIdx.x * blockDim.x + threadIdx.x;
    if (n >= NN) return;
    int b = batch[n];
    float e = expf(g_raw[n] - g_gmax[b]);
    g_score[n] = e;
    atomicAdd(&g_gz[b], e);
}

__global__ void k_score(const int* __restrict__ batch) {
    int n = blockIdx.x * blockDim.x + threadIdx.x;
    if (n >= NN) return;
    int b = batch[n];
    float s = g_score[n] / g_gz[b];
    g_score[n] = s;
    atomicMaxF(&g_gsmax[b], s);
}

// mask, KL terms, counters; also zero agg rows only where needed.
__global__ void k_mask(const int* __restrict__ batch, const float* __restrict__ attn) {
    int n = blockIdx.x * blockDim.x + threadIdx.x;
    if (n >= NN) return;
    int b = batch[n];
    float s = g_score[n];
    float thresh = fminf(g_gsmax[b] - 1e-7f, 0.05f);
    bool m = s > thresh;
    g_mask[n] = m ? 1 : 0;
    if (m) {
        atomicAdd(&g_cnt[b], 1.0f);
        float a = attn[n];
        atomicAdd(&g_kl[b], a * (logf(a) - logf(s + 1e-14f)));
        atomicAdd(&g_nkept, 1);
        float4 z = make_float4(0.f, 0.f, 0.f, 0.f);
        float4* a1 = &g_agg1[n * 32];
        #pragma unroll
        for (int i = 0; i < 32; i++) a1[i] = z;
        float4* a2 = &g_agg2[n * 16];
        #pragma unroll
        for (int i = 0; i < 16; i++) a2[i] = z;
    }
}

// Scatter 1: agg1[dst] += x[src] for edges whose dst is kept.
__global__ void k_scat1(const int* __restrict__ ei, const float4* __restrict__ x4) {
    __shared__ int list[256];
    __shared__ int scnt;
    if (threadIdx.x == 0) scnt = 0;
    __syncthreads();
    int e = blockIdx.x * 256 + threadIdx.x;
    if (e < EE) {
        int dst = ei[EE + e];
        if (g_mask[dst]) {
            int p = atomicAdd(&scnt, 1);
            list[p] = e;
        }
    }
    __syncthreads();
    int nk = scnt;
    int wid = threadIdx.x >> 5;
    int lane = threadIdx.x & 31;
    for (int i = wid; i < nk; i += 8) {
        int ee = list[i];
        int s = ei[ee];
        int d = ei[EE + ee];
        float4 v = x4[s * 32 + lane];
        red_add_v4(&g_agg1[d * 32 + lane], v);
    }
}

// GIN1 MLP for kept nodes: out1 = relu(relu((x+agg1)@W1+b1)@W2+b2) * score
__global__ void k_gin1(const float* __restrict__ x,
                       const float* __restrict__ W1, const float* __restrict__ b1,
                       const float* __restrict__ W2, const float* __restrict__ b2) {
    __shared__ float sh[4][CC];
    __shared__ float st[4][HH];
    int local = threadIdx.x >> 6;         // 0..3
    int j = threadIdx.x & 63;             // 0..63
    int n = blockIdx.x * 4 + local;
    bool active = (n < NN) && g_mask[n];
    if (active) {
        const float* a1 = (const float*)&g_agg1[n * 32];
        for (int k = j; k < CC; k += 64) sh[local][k] = x[n * CC + k] + a1[k];
    }
    __syncthreads();
    if (active) {
        float t = b1[j];
        #pragma unroll 8
        for (int k = 0; k < CC; k++) t = fmaf(sh[local][k], __ldg(&W1[k * HH + j]), t);
        st[local][j] = fmaxf(t, 0.f);
    }
    __syncthreads();
    if (active) {
        float o = b2[j];
        #pragma unroll 8
        for (int k = 0; k < HH; k++) o = fmaf(st[local][k], __ldg(&W2[k * HH + j]), o);
        o = fmaxf(o, 0.f);
        ((float*)&g_out1[n * 16])[j] = o * g_score[n];
    }
}

// Scatter 2: agg2[dst] += out1[src] for edges with both endpoints kept.
__global__ void k_scat2(const int* __restrict__ ei) {
    __shared__ int list[256];
    __shared__ int scnt;
    if (threadIdx.x == 0) scnt = 0;
    __syncthreads();
    int e = blockIdx.x * 256 + threadIdx.x;
    if (e < EE) {
        int s = ei[e];
        int d = ei[EE + e];
        if (g_mask[s] && g_mask[d]) {
            int p = atomicAdd(&scnt, 1);
            list[p] = e;
        }
    }
    __syncthreads();
    int nk = scnt;
    int wid = threadIdx.x >> 5;
    int lane = threadIdx.x & 31;
    for (int i = wid; i < nk; i += 8) {
        if (lane < 16) {
            int ee = list[i];
            int s = ei[ee];
            int d = ei[EE + ee];
            float4 v = g_out1[s * 16 + lane];
            red_add_v4(&g_agg2[d * 16 + lane], v);
        }
    }
}

// GIN2 MLP for kept nodes + atomic accumulate into graph_out.
__global__ void k_gin2(const int* __restrict__ batch,
                       const float* __restrict__ W3, const float* __restrict__ b3,
                       const float* __restrict__ W4, const float* __restrict__ b4) {
    __shared__ float sh[4][HH];
    __shared__ float st[4][HH];
    int local = threadIdx.x >> 6;
    int j = threadIdx.x & 63;
    int n = blockIdx.x * 4 + local;
    bool active = (n < NN) && g_mask[n];
    if (active) {
        const float* o1 = (const float*)&g_out1[n * 16];
        const float* a2 = (const float*)&g_agg2[n * 16];
        sh[local][j] = o1[j] + a2[j];
    }
    __syncthreads();
    if (active) {
        float t = b3[j];
        #pragma unroll 8
        for (int k = 0; k < HH; k++) t = fmaf(sh[local][k], __ldg(&W3[k * HH + j]), t);
        st[local][j] = fmaxf(t, 0.f);
    }
    __syncthreads();
    if (active) {
        float o = b4[j];
        #pragma unroll 8
        for (int k = 0; k < HH; k++) o = fmaf(st[local][k], __ldg(&W4[k * HH + j]), o);
        o = fmaxf(o, 0.f);
        atomicAdd(&g_go[batch[n] * HH + j], o);
    }
}

// Final: pred, attn_loss, ratio -> d_out
__global__ void k_final(const float* __restrict__ Wl, const float* __restrict__ bl,
                        float* __restrict__ out) {
    int g = threadIdx.x;
    if (g < GG) {
        float p = bl[0];
        #pragma unroll 8
        for (int k = 0; k < HH; k++) p = fmaf(g_go[g * HH + k], Wl[k], p);
        out[g] = p;
        out[GG + g] = g_kl[g] / fmaxf(g_cnt[g], 1.0f);
    }
    if (g == 0) out[2 * GG] = (float)g_nkept / (float)NN;
}

// ---------------- launch ----------------
extern "C" void kernel_launch(void* const* d_in, const int* in_sizes, int n_in,
                              void* d_out, int out_size) {
    const float* x      = (const float*)d_in[0];
    const int*   ei     = (const int*)d_in[1];
    const int*   batch  = (const int*)d_in[2];
    const float* attn   = (const float*)d_in[3];
    const float* W1     = (const float*)d_in[4];
    const float* b1     = (const float*)d_in[5];
    const float* W2     = (const float*)d_in[6];
    const float* b2     = (const float*)d_in[7];
    const float* pool_w = (const float*)d_in[8];
    const float* W3     = (const float*)d_in[9];
    const float* b3     = (const float*)d_in[10];
    const float* W4     = (const float*)d_in[11];
    const float* b4     = (const float*)d_in[12];
    const float* Wl     = (const float*)d_in[13];
    const float* bl     = (const float*)d_in[14];
    float* out = (float*)d_out;

    k_init<<<(GG * HH + 255) / 256, 256>>>();
    k_raw<<<(NN * 32 + 255) / 256, 256>>>((const float4*)x, (const float4*)pool_w, batch);
    k_exp<<<(NN + 255) / 256, 256>>>(batch);
    k_score<<<(NN + 255) / 256, 256>>>(batch);
    k_mask<<<(NN + 255) / 256, 256>>>(batch, attn);
    k_scat1<<<(EE + 255) / 256, 256>>>(ei, (const float4*)x);
    k_gin1<<<(NN + 3) / 4, 256>>>(x, W1, b1, W2, b2);
    k_scat2<<<(EE + 255) / 256, 256>>>(ei);
    k_gin2<<<(NN + 3) / 4, 256>>>(batch, W3, b3, W4, b4);
    k_final<<<1, 512>>>(Wl, bl, out);
}

// round 2
// speedup vs baseline: 3.2515x; 3.2515x over previous
#include <cuda_runtime.h>
#include <math.h>

#define NN 100000
#define EE 1600000
#define CC 128
#define HH 64
#define GG 512

// ---------------- scratch (device globals: allocation-free) ----------------
__device__ float4 g_agg1[NN * (CC / 4)];   // zeroed only at kept rows
__device__ float4 g_out1[NN * (HH / 4)];   // written only at kept rows
__device__ float4 g_agg2[NN * (HH / 4)];   // zeroed only at kept rows
__device__ float g_raw[NN];
__device__ float g_score[NN];
__device__ unsigned char g_mask[NN];
__device__ float g_klval[GG];
__device__ float g_cntval[GG];
__device__ float g_go[GG * HH];
__device__ int g_kept[NN];
__device__ int g_elist[EE];
__device__ int g_nkept;
__device__ int g_n2;

// ---------------- helpers ----------------
__device__ __forceinline__ void red_add_v4(float4* a, float4 v) {
    asm volatile("red.global.add.v4.f32 [%0], {%1,%2,%3,%4};"
                 :: "l"(a), "f"(v.x), "f"(v.y), "f"(v.z), "f"(v.w) : "memory");
}

// ---------------- kernels ----------------
__global__ void k_init() {
    g_nkept = 0;
    g_n2 = 0;
}

// raw[n] = dot(x[n], pool_w). One warp per node, fully coalesced float4.
__global__ void k_raw(const float4* __restrict__ x4, const float4* __restrict__ pw4) {
    int gt = blockIdx.x * blockDim.x + threadIdx.x;
    int n = gt >> 5;
    int lane = gt & 31;
    if (n >= NN) return;
    float4 v = x4[n * 32 + lane];
    float4 w = pw4[lane];
    float s = v.x * w.x + v.y * w.y + v.z * w.z + v.w * w.w;
    #pragma unroll
    for (int o = 16; o; o >>= 1) s += __shfl_down_sync(0xffffffffu, s, o);
    if (lane == 0) g_raw[n] = s;
}

// One block per graph: segment softmax, mask, KL, cnt, kept-list, agg zeroing.
// batch is sorted, so each graph's nodes are a contiguous range found by binary search.
__global__ void k_soft(const int* __restrict__ batch, const float* __restrict__ attn) {
    int b = blockIdx.x;
    int t = threadIdx.x;
    __shared__ int s_se[2];
    __shared__ float red[256];
    if (t < 2) {
        int target = b + t;
        int lo = 0, hi = NN;
        while (lo < hi) { int mid = (lo + hi) >> 1; if (batch[mid] < target) lo = mid + 1; else hi = mid; }
        s_se[t] = lo;
    }
    // zero this graph's output accumulator (removes separate memset + atomic init)
    for (int k = t; k < HH; k += 256) g_go[b * HH + k] = 0.f;
    __syncthreads();
    int start = s_se[0], end = s_se[1];

    // pass 1: max
    float m = -INFINITY;
    for (int i = start + t; i < end; i += 256) m = fmaxf(m, g_raw[i]);
    red[t] = m; __syncthreads();
    for (int o = 128; o; o >>= 1) { if (t < o) red[t] = fmaxf(red[t], red[t + o]); __syncthreads(); }
    m = red[0]; __syncthreads();

    // pass 2: exp + sum
    float sum = 0.f;
    for (int i = start + t; i < end; i += 256) {
        float e = expf(g_raw[i] - m);
        g_score[i] = e;
        sum += e;
    }
    red[t] = sum; __syncthreads();
    for (int o = 128; o; o >>= 1) { if (t < o) red[t] += red[t + o]; __syncthreads(); }
    float z = red[0]; __syncthreads();

    // pass 3: normalize + smax
    float smax = 0.f;
    for (int i = start + t; i < end; i += 256) {
        float s = g_score[i] / z;
        g_score[i] = s;
        smax = fmaxf(smax, s);
    }
    red[t] = smax; __syncthreads();
    for (int o = 128; o; o >>= 1) { if (t < o) red[t] = fmaxf(red[t], red[t + o]); __syncthreads(); }
    smax = red[0]; __syncthreads();

    float thresh = fminf(smax - 1e-7f, 0.05f);

    // pass 4: mask, KL, cnt, kept-list append, zero agg rows of kept nodes
    float kl = 0.f, cnt = 0.f;
    for (int i = start + t; i < end; i += 256) {
        float s = g_score[i];
        bool keep = s > thresh;
        g_mask[i] = keep ? 1 : 0;
        if (keep) {
            cnt += 1.f;
            float a = attn[i];
            kl += a * (logf(a) - logf(s + 1e-14f));
            int p = atomicAdd(&g_nkept, 1);
            g_kept[p] = i;
            float4 zz = make_float4(0.f, 0.f, 0.f, 0.f);
            float4* a1 = &g_agg1[(size_t)i * 32];
            #pragma unroll
            for (int q = 0; q < 32; q++) a1[q] = zz;
            float4* a2 = &g_agg2[(size_t)i * 16];
            #pragma unroll
            for (int q = 0; q < 16; q++) a2[q] = zz;
        }
    }
    red[t] = kl; __syncthreads();
    for (int o = 128; o; o >>= 1) { if (t < o) red[t] += red[t + o]; __syncthreads(); }
    if (t == 0) g_klval[b] = red[0];
    __syncthreads();
    red[t] = cnt; __syncthreads();
    for (int o = 128; o; o >>= 1) { if (t < o) red[t] += red[t + o]; __syncthreads(); }
    if (t == 0) g_cntval[b] = red[0];
}

// Single edge scan: scatter-1 for dst-kept edges (inline), and emit both-kept
// edge list for scatter-2.
__global__ void k_edges(const int* __restrict__ ei, const float4* __restrict__ x4) {
    __shared__ int list[256];
    __shared__ int scnt;
    if (threadIdx.x == 0) scnt = 0;
    __syncthreads();
    int e = blockIdx.x * 256 + threadIdx.x;
    if (e < EE) {
        int d = ei[EE + e];
        if (g_mask[d]) {
            int s = ei[e];
            int p = atomicAdd(&scnt, 1);
            list[p] = e;
            if (g_mask[s]) {
                int q = atomicAdd(&g_n2, 1);
                g_elist[q] = e;
            }
        }
    }
    __syncthreads();
    int nk = scnt;
    int wid = threadIdx.x >> 5;
    int lane = threadIdx.x & 31;
    for (int i = wid; i < nk; i += 8) {
        int ee = list[i];
        int s = ei[ee];
        int d = ei[EE + ee];
        red_add_v4(&g_agg1[(size_t)d * 32 + lane], x4[(size_t)s * 32 + lane]);
    }
}

// GIN1 MLP only for kept nodes (grid-stride over device-side kept list).
__global__ void k_gin1(const float* __restrict__ x,
                       const float* __restrict__ W1, const float* __restrict__ b1,
                       const float* __restrict__ W2, const float* __restrict__ b2) {
    __shared__ float sh[4][CC];
    __shared__ float st[4][HH];
    int local = threadIdx.x >> 6;
    int j = threadIdx.x & 63;
    int nk = g_nkept;
    for (int base = blockIdx.x * 4; base < nk; base += gridDim.x * 4) {
        int idx = base + local;
        int n = (idx < nk) ? g_kept[idx] : -1;
        if (n >= 0) {
            const float* a1 = (const float*)&g_agg1[(size_t)n * 32];
            for (int k = j; k < CC; k += 64) sh[local][k] = x[(size_t)n * CC + k] + a1[k];
        }
        __syncthreads();
        if (n >= 0) {
            float tt = b1[j];
            #pragma unroll 8
            for (int k = 0; k < CC; k++) tt = fmaf(sh[local][k], __ldg(&W1[k * HH + j]), tt);
            st[local][j] = fmaxf(tt, 0.f);
        }
        __syncthreads();
        if (n >= 0) {
            float o = b2[j];
            #pragma unroll 8
            for (int k = 0; k < HH; k++) o = fmaf(st[local][k], __ldg(&W2[k * HH + j]), o);
            o = fmaxf(o, 0.f);
            ((float*)&g_out1[(size_t)n * 16])[j] = o * g_score[n];
        }
        __syncthreads();
    }
}

// Scatter 2: only over the compacted both-kept edge list (tiny).
__global__ void k_scat2(const int* __restrict__ ei) {
    int n2 = g_n2;
    int gw = (blockIdx.x * blockDim.x + threadIdx.x) >> 5;
    int lane = threadIdx.x & 31;
    int nw = (gridDim.x * blockDim.x) >> 5;
    for (int i = gw; i < n2; i += nw) {
        int e = g_elist[i];
        int s = ei[e];
        int d = ei[EE + e];
        if (lane < 16)
            red_add_v4(&g_agg2[(size_t)d * 16 + lane], g_out1[(size_t)s * 16 + lane]);
    }
}

// GIN2 MLP for kept nodes + atomic accumulate into graph_out (≈1 kept/graph → no contention).
__global__ void k_gin2(const int* __restrict__ batch,
                       const float* __restrict__ W3, const float* __restrict__ b3,
                       const float* __restrict__ W4, const float* __restrict__ b4) {
    __shared__ float sh[4][HH];
    __shared__ float st[4][HH];
    int local = threadIdx.x >> 6;
    int j = threadIdx.x & 63;
    int nk = g_nkept;
    for (int base = blockIdx.x * 4; base < nk; base += gridDim.x * 4) {
        int idx = base + local;
        int n = (idx < nk) ? g_kept[idx] : -1;
        if (n >= 0) {
            const float* o1 = (const float*)&g_out1[(size_t)n * 16];
            const float* a2 = (const float*)&g_agg2[(size_t)n * 16];
            sh[local][j] = o1[j] + a2[j];
        }
        __syncthreads();
        if (n >= 0) {
            float tt = b3[j];
            #pragma unroll 8
            for (int k = 0; k < HH; k++) tt = fmaf(sh[local][k], __ldg(&W3[k * HH + j]), tt);
            st[local][j] = fmaxf(tt, 0.f);
        }
        __syncthreads();
        if (n >= 0) {
            float o = b4[j];
            #pragma unroll 8
            for (int k = 0; k < HH; k++) o = fmaf(st[local][k], __ldg(&W4[k * HH + j]), o);
            o = fmaxf(o, 0.f);
            atomicAdd(&g_go[batch[n] * HH + j], o);
        }
        __syncthreads();
    }
}

// Final: pred, attn_loss, ratio -> d_out
__global__ void k_final(const float* __restrict__ Wl, const float* __restrict__ bl,
                        float* __restrict__ out) {
    int g = threadIdx.x + blockIdx.x * blockDim.x;
    if (g < GG) {
        float p = bl[0];
        #pragma unroll 8
        for (int k = 0; k < HH; k++) p = fmaf(g_go[g * HH + k], Wl[k], p);
        out[g] = p;
        out[GG + g] = g_klval[g] / fmaxf(g_cntval[g], 1.0f);
    }
    if (g == 0) out[2 * GG] = (float)g_nkept / (float)NN;
}

// ---------------- launch ----------------
extern "C" void kernel_launch(void* const* d_in, const int* in_sizes, int n_in,
                              void* d_out, int out_size) {
    const float* x      = (const float*)d_in[0];
    const int*   ei     = (const int*)d_in[1];
    const int*   batch  = (const int*)d_in[2];
    const float* attn   = (const float*)d_in[3];
    const float* W1     = (const float*)d_in[4];
    const float* b1     = (const float*)d_in[5];
    const float* W2     = (const float*)d_in[6];
    const float* b2     = (const float*)d_in[7];
    const float* pool_w = (const float*)d_in[8];
    const float* W3     = (const float*)d_in[9];
    const float* b3     = (const float*)d_in[10];
    const float* W4     = (const float*)d_in[11];
    const float* b4     = (const float*)d_in[12];
    const float* Wl     = (const float*)d_in[13];
    const float* bl     = (const float*)d_in[14];
    float* out = (float*)d_out;

    k_init<<<1, 1>>>();
    k_raw<<<(NN * 32 + 255) / 256, 256>>>((const float4*)x, (const float4*)pool_w);
    k_soft<<<GG, 256>>>(batch, attn);
    k_edges<<<(EE + 255) / 256, 256>>>(ei, (const float4*)x);
    k_gin1<<<256, 256>>>(x, W1, b1, W2, b2);
    k_scat2<<<16, 256>>>(ei);
    k_gin2<<<128, 256>>>(batch, W3, b3, W4, b4);
    k_final<<<2, 256>>>(Wl, bl, out);
}